// round 12
// baseline (speedup 1.0000x reference)
#include <cuda_runtime.h>
#include <cuda_fp16.h>

// Problem constants
#define VOCAB 50257
#define EMB   128
#define MEM   256   // memory slots (M)
#define BATCH 16    // batch (B)
#define SENT  64    // sentence length (S)
#define TBL   ((size_t)VOCAB * EMB)
#define TBL_I8 (TBL / 8)            // 804112 uint4 items per table
#define FULLMASK 0xffffffffu

// Static scratch:
//  g_Ch   : fp16 copies of tables C1..C3 (38.6 MB)
//  g_E    : E_t[b][m][d] fp32 (6.3 MB)
//  g_u1   : hop-0 state;  g_prob : hop-2 attention weights
__device__ __align__(16) __half g_Ch[3ULL * VOCAB * EMB];
__device__ __align__(16) float  g_E[3][BATCH][MEM][EMB];
__device__ __align__(16) float  g_u1[BATCH][EMB];
__device__ __align__(16) float  g_prob[BATCH][MEM];

// ---------------------------------------------------------------------------
// Convert one uint4-item (8 fp32 -> 8 fp16) of table tbl (0..2 -> C1..C3).
// ---------------------------------------------------------------------------
__device__ __forceinline__ void convert_item(const float* __restrict__ C,
                                             int tbl, size_t i) {
    const float4* __restrict__ src =
        (const float4*)(C + (size_t)(tbl + 1) * TBL);
    float4 a = __ldg(src + 2 * i);
    float4 b = __ldg(src + 2 * i + 1);
    __half2 h0 = __floats2half2_rn(a.x, a.y);
    __half2 h1 = __floats2half2_rn(a.z, a.w);
    __half2 h2 = __floats2half2_rn(b.x, b.y);
    __half2 h3 = __floats2half2_rn(b.z, b.w);
    uint4 o;
    o.x = *reinterpret_cast<unsigned int*>(&h0);
    o.y = *reinterpret_cast<unsigned int*>(&h1);
    o.z = *reinterpret_cast<unsigned int*>(&h2);
    o.w = *reinterpret_cast<unsigned int*>(&h3);
    ((uint4*)g_Ch)[(size_t)tbl * TBL_I8 + i] = o;
}

// ---------------------------------------------------------------------------
// fp16 gather-sum, PAIRED-TOKEN form: one warp per (t,b,m) unit.
// Per iteration the warp reads TWO token rows (256 B each): lanes 0-15 cover
// row A, lanes 16-31 cover row B, 16 B (uint4 = 8 halves) per lane.
// 32 iterations x 512 B — same load structure as the LTS-capped fp32 loop.
// Final xor-16 combine merges the two half-warp partial sums. E stored fp32.
// ---------------------------------------------------------------------------
__device__ __forceinline__ void gather_unit_h(const int* __restrict__ story,
                                              int t, int b, int m, int lane) {
    const int* toks = story + ((size_t)m * BATCH + b) * SENT;
    const int tok_lo = toks[lane];
    const int tok_hi = toks[lane + 32];

    const uint4* __restrict__ tab =
        (const uint4*)g_Ch + (size_t)t * VOCAB * (EMB / 8);   // 16 uint4/row
    const int hs  = lane >> 4;     // half-select: 0 = even token, 1 = odd
    const int col = lane & 15;     // 16B chunk within the row

    float4 accA = make_float4(0.f, 0.f, 0.f, 0.f);
    float4 accB = make_float4(0.f, 0.f, 0.f, 0.f);

#pragma unroll
    for (int i = 0; i < 16; i++) {              // tokens 0..31
        int tok = __shfl_sync(FULLMASK, tok_lo, 2 * i + hs);
        uint4 v = __ldg(tab + (size_t)tok * 16 + col);
        float2 f0 = __half22float2(*reinterpret_cast<__half2*>(&v.x));
        float2 f1 = __half22float2(*reinterpret_cast<__half2*>(&v.y));
        float2 f2 = __half22float2(*reinterpret_cast<__half2*>(&v.z));
        float2 f3 = __half22float2(*reinterpret_cast<__half2*>(&v.w));
        accA.x += f0.x; accA.y += f0.y; accA.z += f1.x; accA.w += f1.y;
        accB.x += f2.x; accB.y += f2.y; accB.z += f3.x; accB.w += f3.y;
    }
#pragma unroll
    for (int i = 0; i < 16; i++) {              // tokens 32..63
        int tok = __shfl_sync(FULLMASK, tok_hi, 2 * i + hs);
        uint4 v = __ldg(tab + (size_t)tok * 16 + col);
        float2 f0 = __half22float2(*reinterpret_cast<__half2*>(&v.x));
        float2 f1 = __half22float2(*reinterpret_cast<__half2*>(&v.y));
        float2 f2 = __half22float2(*reinterpret_cast<__half2*>(&v.z));
        float2 f3 = __half22float2(*reinterpret_cast<__half2*>(&v.w));
        accA.x += f0.x; accA.y += f0.y; accA.z += f1.x; accA.w += f1.y;
        accB.x += f2.x; accB.y += f2.y; accB.z += f3.x; accB.w += f3.y;
    }

    // merge half-warp partials (lane l and l^16 hold identical dims)
    accA.x += __shfl_xor_sync(FULLMASK, accA.x, 16);
    accA.y += __shfl_xor_sync(FULLMASK, accA.y, 16);
    accA.z += __shfl_xor_sync(FULLMASK, accA.z, 16);
    accA.w += __shfl_xor_sync(FULLMASK, accA.w, 16);
    accB.x += __shfl_xor_sync(FULLMASK, accB.x, 16);
    accB.y += __shfl_xor_sync(FULLMASK, accB.y, 16);
    accB.z += __shfl_xor_sync(FULLMASK, accB.z, 16);
    accB.w += __shfl_xor_sync(FULLMASK, accB.w, 16);

    if (hs == 0) {
        float4* row = (float4*)g_E[t][b][m];    // dims [col*8 .. col*8+8)
        row[2 * col]     = accA;
        row[2 * col + 1] = accB;
    }
}

// ---------------------------------------------------------------------------
// hop0 for batch b, 256 threads: g_u1[b] = mean_m E0[b][m]
// ---------------------------------------------------------------------------
__device__ __forceinline__ void hop0_256(int b) {
    __shared__ float4 wp0[8][32];
    const int tid = threadIdx.x, w = tid >> 5, lane = tid & 31;
    const float4* __restrict__ E0 = (const float4*)g_E[0][b];

    float4 acc = make_float4(0.f, 0.f, 0.f, 0.f);
#pragma unroll 4
    for (int k = 0; k < 32; k++) {
        float4 v = E0[(size_t)(w * 32 + k) * 32 + lane];
        acc.x += v.x; acc.y += v.y; acc.z += v.z; acc.w += v.w;
    }
    wp0[w][lane] = acc;
    __syncthreads();
    if (tid < 32) {
        float4 a = wp0[0][tid];
#pragma unroll
        for (int i = 1; i < 8; i++) {
            float4 c = wp0[i][tid];
            a.x += c.x; a.y += c.y; a.z += c.z; a.w += c.w;
        }
        a.x *= (1.f / MEM); a.y *= (1.f / MEM); a.z *= (1.f / MEM); a.w *= (1.f / MEM);
        ((float4*)g_u1[b])[tid] = a;
    }
}

// ---------------------------------------------------------------------------
// logits + softmax: prob[m] = softmax_m( Ep[m] . us )  (256 threads)
// ---------------------------------------------------------------------------
__device__ __forceinline__ void logits_softmax(const float4* __restrict__ Ep,
                                               const float4* us,
                                               float* prob, float* red) {
    const int tid = threadIdx.x, w = tid >> 5, lane = tid & 31;
    const int q = lane & 3, sl = lane >> 2;
#pragma unroll
    for (int pass = 0; pass < 4; pass++) {
        const int m = pass * 64 + w * 8 + sl;
        float pd = 0.f;
#pragma unroll
        for (int j = 0; j < 8; j++) {
            float4 e  = Ep[(size_t)m * 32 + q + 4 * j];
            float4 uu = us[q + 4 * j];
            pd += e.x * uu.x + e.y * uu.y + e.z * uu.z + e.w * uu.w;
        }
        pd += __shfl_xor_sync(FULLMASK, pd, 1);
        pd += __shfl_xor_sync(FULLMASK, pd, 2);
        if (q == 0) prob[m] = pd;
    }
    __syncthreads();

    float x = prob[tid];
    float mx = x;
#pragma unroll
    for (int off = 16; off; off >>= 1)
        mx = fmaxf(mx, __shfl_xor_sync(FULLMASK, mx, off));
    if (lane == 0) red[w] = mx;
    __syncthreads();
    mx = red[0];
#pragma unroll
    for (int i = 1; i < 8; i++) mx = fmaxf(mx, red[i]);
    __syncthreads();

    float ev = __expf(x - mx);
    float sv = ev;
#pragma unroll
    for (int off = 16; off; off >>= 1)
        sv += __shfl_xor_sync(FULLMASK, sv, off);
    if (lane == 0) red[w] = sv;
    __syncthreads();
    float tot = red[0];
#pragma unroll
    for (int i = 1; i < 8; i++) tot += red[i];

    prob[tid] = ev / tot;
    __syncthreads();
}

// ---------------------------------------------------------------------------
// L1: convert C1 (DRAM-bound pipeline fill).
// ---------------------------------------------------------------------------
__global__ void __launch_bounds__(256) l1_kernel(const float* __restrict__ C) {
    size_t i = (size_t)blockIdx.x * 256 + threadIdx.x;
    if (i < TBL_I8) convert_item(C, 0, i);
}

// ---------------------------------------------------------------------------
// L2: gather t0 (blocks 0..511, L2-stream) || convert C2 (512..1535, DRAM).
// ---------------------------------------------------------------------------
__global__ void __launch_bounds__(256) l2_kernel(const int* __restrict__ story,
                                                 const float* __restrict__ C) {
    if (blockIdx.x < 512) {
        const int w = blockIdx.x * 8 + (threadIdx.x >> 5);
        gather_unit_h(story, 0, w / MEM, w % MEM, threadIdx.x & 31);
    } else {
        size_t i = (size_t)(blockIdx.x - 512) * 256 + threadIdx.x;
        const size_t stride = 1024 * 256;
        for (; i < TBL_I8; i += stride) convert_item(C, 1, i);
    }
}

// ---------------------------------------------------------------------------
// L3: hop0 (0..15) || gather t1 (16..527) || convert C3 (528..1551).
// ---------------------------------------------------------------------------
__global__ void __launch_bounds__(256) l3_kernel(const int* __restrict__ story,
                                                 const float* __restrict__ C) {
    if (blockIdx.x < 16) {
        hop0_256(blockIdx.x);
    } else if (blockIdx.x < 528) {
        const int w = (blockIdx.x - 16) * 8 + (threadIdx.x >> 5);
        gather_unit_h(story, 1, w / MEM, w % MEM, threadIdx.x & 31);
    } else {
        size_t i = (size_t)(blockIdx.x - 528) * 256 + threadIdx.x;
        const size_t stride = 1024 * 256;
        for (; i < TBL_I8; i += stride) convert_item(C, 2, i);
    }
}

// ---------------------------------------------------------------------------
// L4: blocks 0..15: hop1 (u2 = u1 + attn(E0;E1)), out[b] = u2, then
//     prob2 = softmax(E1 . u2) -> g_prob[b].  Blocks 16..527: gather t2.
// ---------------------------------------------------------------------------
__global__ void __launch_bounds__(256) l4_kernel(const int* __restrict__ story,
                                                 float* __restrict__ out) {
    if (blockIdx.x >= 16) {
        const int w = (blockIdx.x - 16) * 8 + (threadIdx.x >> 5);
        gather_unit_h(story, 2, w / MEM, w % MEM, threadIdx.x & 31);
        return;
    }

    __shared__ float4 us[32];
    __shared__ float4 us2[32];
    __shared__ float  prob[MEM];
    __shared__ float4 wp[8][32];
    __shared__ float  red[8];

    const int b = blockIdx.x, tid = threadIdx.x, w = tid >> 5, lane = tid & 31;
    const float4* __restrict__ E0 = (const float4*)g_E[0][b];
    const float4* __restrict__ E1 = (const float4*)g_E[1][b];

    if (tid < 32) us[tid] = ((const float4*)g_u1[b])[tid];
    __syncthreads();

    logits_softmax(E0, us, prob, red);          // prob1

    {   // o1 = sum prob1*E1; u2 = u1 + o1; out = u2
        float4 acc = make_float4(0.f, 0.f, 0.f, 0.f);
#pragma unroll 4
        for (int k = 0; k < 32; k++) {
            const int mm = w * 32 + k;
            float p = prob[mm];
            float4 v = E1[(size_t)mm * 32 + lane];
            acc.x += p * v.x; acc.y += p * v.y; acc.z += p * v.z; acc.w += p * v.w;
        }
        wp[w][lane] = acc;
        __syncthreads();
        if (tid < 32) {
            float4 a = wp[0][tid];
#pragma unroll
            for (int i = 1; i < 8; i++) {
                float4 c = wp[i][tid];
                a.x += c.x; a.y += c.y; a.z += c.z; a.w += c.w;
            }
            float4 uu = us[tid];
            a.x += uu.x; a.y += uu.y; a.z += uu.z; a.w += uu.w;
            us2[tid] = a;
            ((float4*)out)[(size_t)b * 32 + tid] = a;   // L5 adds o2
        }
        __syncthreads();
    }

    logits_softmax(E1, us2, prob, red);         // prob2
    g_prob[b][tid] = prob[tid];
}

// ---------------------------------------------------------------------------
// L5: out[b] += sum_m prob2[m] * E2[b][m]; 8 blocks per batch, atomic merge.
// ---------------------------------------------------------------------------
__global__ void __launch_bounds__(256) l5_kernel(float* __restrict__ out) {
    __shared__ float4 wp[8][32];
    const int b = blockIdx.x >> 3, chunk = blockIdx.x & 7;
    const int tid = threadIdx.x, w = tid >> 5, lane = tid & 31;
    const float4* __restrict__ E2 = (const float4*)g_E[2][b];

    float4 acc = make_float4(0.f, 0.f, 0.f, 0.f);
#pragma unroll
    for (int k = 0; k < 4; k++) {
        const int m = chunk * 32 + w * 4 + k;
        float p = __ldg(&g_prob[b][m]);
        float4 v = E2[(size_t)m * 32 + lane];
        acc.x += p * v.x; acc.y += p * v.y; acc.z += p * v.z; acc.w += p * v.w;
    }
    wp[w][lane] = acc;
    __syncthreads();
    if (tid < 32) {
        float4 a = wp[0][tid];
#pragma unroll
        for (int i = 1; i < 8; i++) {
            float4 c = wp[i][tid];
            a.x += c.x; a.y += c.y; a.z += c.z; a.w += c.w;
        }
        float* dst = out + (size_t)b * EMB + tid * 4;
        atomicAdd(dst + 0, a.x); atomicAdd(dst + 1, a.y);
        atomicAdd(dst + 2, a.z); atomicAdd(dst + 3, a.w);
    }
}

extern "C" void kernel_launch(void* const* d_in, const int* in_sizes, int n_in,
                              void* d_out, int out_size) {
    const int*   story = (const int*)d_in[0];   // (256, 16, 64) int32
    const float* C     = (const float*)d_in[1]; // (4, 50257, 128) fp32
    float*       out   = (float*)d_out;         // (16, 128) fp32

    (void)in_sizes; (void)n_in; (void)out_size;

    l1_kernel<<<3142, 256>>>(C);                 // conv C1
    l2_kernel<<<1536, 256>>>(story, C);          // gather t0 || conv C2
    l3_kernel<<<1552, 256>>>(story, C);          // hop0 || gather t1 || conv C3
    l4_kernel<<<528, 256>>>(story, out);         // hop1+logits2 || gather t2
    l5_kernel<<<128, 256>>>(out);                // out += weighted-sum(E2)
}